// round 16
// baseline (speedup 1.0000x reference)
#include <cuda_runtime.h>
#include <stdint.h>

// Problem constants (fixed by the dataset: B=32, V=200000, F=400000).
#define BB   32
#define VV   200000
#define FF   400000
#define NV   (BB * VV)      // 6,400,000
#define GB   4              // batches per group (lane sub-group)  [deep pipeline]
#define NGRP (BB / GB)      // 8 groups

// Batch-transposed layouts (index = (g*VV + v)*GB + j):
//   gathers:  g_vtx4  float4 (1 LDG.128 per vertex)
//   scatters: g_accXY float2 + g_accZ float
__device__ float4 g_vtx4 [NV];
__device__ float2 g_accXY[NV];
__device__ float  g_accZ [NV];

__device__ __forceinline__ void red_add_v2(float2* addr, float x, float y) {
    asm volatile("red.global.add.v2.f32 [%0], {%1, %2};"
                 :: "l"(addr), "f"(x), "f"(y) : "memory");
}
__device__ __forceinline__ void red_add_f(float* addr, float z) {
    asm volatile("red.global.add.f32 [%0], %1;"
                 :: "l"(addr), "f"(z) : "memory");
}

// Smem staging: 4 batch rows x 776 floats (768 data + 8 pad).
// 776 % 4 == 0 (float4 alignment); 776 mod 32 == 8 -> bank = (8j + 3vl + c)
// conflict-free for the write-phase pattern (j in 0..3, vl in 0..7 per warp).
#define SROW   776
#define VPB    256                      // vertices per DRAM block
#define VBLOCKS ((VV + VPB - 1) / VPB)  // 782
#define ABLOCKS (FF * GB / 2 / 256)     // 3125  (2 faces per thread)

// ---------------------------------------------------------------------------
// Body 1: transpose-repack 256 vertices x 4 batches of group g, zero acc.
// No grid-dependency sync (fills predecessor tail under PDL).
// ---------------------------------------------------------------------------
__device__ __forceinline__ void repack_body(const float* __restrict__ verts,
                                            int g, int bx, float* s) {
    float4* s4 = reinterpret_cast<float4*>(s);
    const int t  = threadIdx.x;
    const int v0 = bx * VPB;
    const bool full = (v0 + VPB <= VV);

    if (full) {
        // 4 rows x 192 float4 = 768 float4, 3 per thread.
#pragma unroll
        for (int rr = 0; rr < 3; rr++) {
            int idx   = rr * 256 + t;          // 0..767
            int b_loc = idx / 192;
            int k     = idx - b_loc * 192;
            const float4* src = reinterpret_cast<const float4*>(
                verts + (size_t)(g * GB + b_loc) * VV * 3 + (size_t)v0 * 3);
            s4[b_loc * (SROW / 4) + k] = src[k];
        }
    } else {
        // Tail block: scalar guarded path (4 rows x 768 floats).
        for (int r = 0; r < 12; r++) {
            int idx   = r * 256 + t;           // 0..3071
            int b_loc = idx / 768;
            int off   = idx - b_loc * 768;
            int vl    = off / 3;
            if (v0 + vl < VV) {
                size_t src = (size_t)(g * GB + b_loc) * VV * 3 + (size_t)(v0 + vl) * 3
                             + (off - vl * 3);
                s[b_loc * SROW + off] = verts[src];
            }
        }
    }
    __syncthreads();

    // Write phase: 256 verts x 4 slots = 1024 items, 4 per thread.
#pragma unroll
    for (int it = 0; it < 4; it++) {
        int w  = it * 256 + t;
        int vl = w >> 2;
        int j  = w & 3;
        int v  = v0 + vl;
        if (v < VV) {
            const float* p = &s[j * SROW + vl * 3];
            uint32_t dst = (uint32_t)(g * VV + v) * GB + j;
            g_vtx4 [dst] = make_float4(p[0], p[1], p[2], 0.0f);
            g_accXY[dst] = make_float2(0.0f, 0.0f);
            g_accZ [dst] = 0.0f;
        }
    }
}

// ---------------------------------------------------------------------------
// Body 2: accumulate face normals for group g. 2 faces per thread, j = t&3.
// Needs repack(g) from the previous launch -> grid-dependency sync.
// ---------------------------------------------------------------------------
__device__ __forceinline__ void accum_body(const int* __restrict__ faces,
                                           int g, int bx) {
#if __CUDA_ARCH__ >= 900
    cudaGridDependencySynchronize();
#endif
    uint32_t t  = (uint32_t)bx * 256 + threadIdx.x;
    uint32_t j  = t & 3;
    uint32_t fp = t >> 2;               // face-pair index, 0..FF/2-1
    uint32_t base = (uint32_t)g * (VV * GB) + j;

    const int2* f2 = reinterpret_cast<const int2*>(faces) + 3 * (size_t)fp;
    int2 q0 = __ldg(&f2[0]);   // a0, a1
    int2 q1 = __ldg(&f2[1]);   // a2, b0
    int2 q2 = __ldg(&f2[2]);   // b1, b2

    uint32_t ia0 = base + (uint32_t)q0.x * GB;
    uint32_t ia1 = base + (uint32_t)q0.y * GB;
    uint32_t ia2 = base + (uint32_t)q1.x * GB;
    uint32_t ib0 = base + (uint32_t)q1.y * GB;
    uint32_t ib1 = base + (uint32_t)q2.x * GB;
    uint32_t ib2 = base + (uint32_t)q2.y * GB;

    float4 va0 = g_vtx4[ia0];
    float4 va1 = g_vtx4[ia1];
    float4 va2 = g_vtx4[ia2];
    float4 vb0 = g_vtx4[ib0];
    float4 vb1 = g_vtx4[ib1];
    float4 vb2 = g_vtx4[ib2];

    // Face A: e1 = v0 - v1; e2 = v2 - v1; n = cross(e2, e1)
    float e1x = va0.x - va1.x, e1y = va0.y - va1.y, e1z = va0.z - va1.z;
    float e2x = va2.x - va1.x, e2y = va2.y - va1.y, e2z = va2.z - va1.z;
    float nax = e2y * e1z - e2z * e1y;
    float nay = e2z * e1x - e2x * e1z;
    float naz = e2x * e1y - e2y * e1x;

    // Face B
    float g1x = vb0.x - vb1.x, g1y = vb0.y - vb1.y, g1z = vb0.z - vb1.z;
    float g2x = vb2.x - vb1.x, g2y = vb2.y - vb1.y, g2z = vb2.z - vb1.z;
    float nbx = g2y * g1z - g2z * g1y;
    float nby = g2z * g1x - g2x * g1z;
    float nbz = g2x * g1y - g2y * g1x;

    red_add_v2(&g_accXY[ia0], nax, nay);  red_add_f(&g_accZ[ia0], naz);
    red_add_v2(&g_accXY[ia1], nax, nay);  red_add_f(&g_accZ[ia1], naz);
    red_add_v2(&g_accXY[ia2], nax, nay);  red_add_f(&g_accZ[ia2], naz);
    red_add_v2(&g_accXY[ib0], nbx, nby);  red_add_f(&g_accZ[ib0], nbz);
    red_add_v2(&g_accXY[ib1], nbx, nby);  red_add_f(&g_accZ[ib1], nbz);
    red_add_v2(&g_accXY[ib2], nbx, nby);  red_add_f(&g_accZ[ib2], nbz);
}

// ---------------------------------------------------------------------------
// Body 3: normalize 256 vertices x 4 batches of group g, write (B, V, 3).
// Grid-dependency sync (needs accum(g) from the previous launch).
// ---------------------------------------------------------------------------
__device__ __forceinline__ void norm_body(float* __restrict__ out,
                                          int g, int bx, float* s) {
#if __CUDA_ARCH__ >= 900
    cudaGridDependencySynchronize();
#endif
    float4* s4 = reinterpret_cast<float4*>(s);
    const int t  = threadIdx.x;
    const int v0 = bx * VPB;
    const bool full = (v0 + VPB <= VV);

#pragma unroll
    for (int it = 0; it < 4; it++) {
        int w  = it * 256 + t;
        int vl = w >> 2;
        int j  = w & 3;
        int v  = v0 + vl;
        if (v < VV) {
            uint32_t src = (uint32_t)(g * VV + v) * GB + j;
            float2 a = g_accXY[src];
            float  z = g_accZ [src];
            float sq = a.x * a.x + a.y * a.y + z * z;
            float sc = rsqrtf(fmaxf(sq, 1e-12f));
            float* p = &s[j * SROW + vl * 3];
            p[0] = a.x * sc;
            p[1] = a.y * sc;
            p[2] = z   * sc;
        }
    }
    __syncthreads();

    if (full) {
#pragma unroll
        for (int rr = 0; rr < 3; rr++) {
            int idx   = rr * 256 + t;
            int b_loc = idx / 192;
            int k     = idx - b_loc * 192;
            float4* dst = reinterpret_cast<float4*>(
                out + (size_t)(g * GB + b_loc) * VV * 3 + (size_t)v0 * 3);
            dst[k] = s4[b_loc * (SROW / 4) + k];
        }
    } else {
        for (int r = 0; r < 12; r++) {
            int idx   = r * 256 + t;
            int b_loc = idx / 768;
            int off   = idx - b_loc * 768;
            int vl    = off / 3;
            if (v0 + vl < VV) {
                size_t dst = (size_t)(g * GB + b_loc) * VV * 3 + (size_t)(v0 + vl) * 3
                             + (off - vl * 3);
                out[dst] = s[b_loc * SROW + off];
            }
        }
    }
}

// ---------------------------------------------------------------------------
// Fused dispatcher — Bresenham proportional interleave (exact counts,
// even spread; statistically neutral vs floor-K but handles all ratios).
// ---------------------------------------------------------------------------
__global__ __launch_bounds__(256) void fused_kernel(
    const float* __restrict__ verts, const int* __restrict__ faces,
    float* __restrict__ out,
    int gA, int nA, int gR, int nR, int gN, int nN) {
    __shared__ float s[GB * SROW];

#if __CUDA_ARCH__ >= 900
    cudaTriggerProgrammaticLaunchCompletion();
#endif

    const int bx = blockIdx.x;
    const int D  = nR + nN;
    int d = -1;
    int a = -1;

    if (nA == 0) {
        d = bx;
    } else if (D == 0) {
        a = bx;
    } else {
        const int T    = nA + D;
        const int prev = (int)(((long long)bx * D) / T);
        const int next = (int)(((long long)(bx + 1) * D) / T);
        if (next > prev) d = prev;
        else             a = bx - prev;
    }

    if (a >= 0) {
        accum_body(faces, gA, a);
    } else if (d < nR) {
        repack_body(verts, gR, d, s);
    } else {
        norm_body(out, gN, d - nR, s);
    }
}

// ---------------------------------------------------------------------------
// 10 PDL-stitched launches — 8-stage software pipeline (half-size bookends):
//   L1:  repack(0)
//   L2:  accum(0) + repack(1)
//   L3..L8: accum(g) + repack(g+1) + norm(g-1)     for g = 1..6
//   L9:  accum(7) + norm(6)
//   L10: norm(7)
// ---------------------------------------------------------------------------
static void launch_fused(int grid, bool pdl,
                         const float* verts, const int* faces, float* out,
                         int gA, int nA, int gR, int nR, int gN, int nN) {
    cudaLaunchConfig_t cfg = {};
    cfg.gridDim  = dim3((unsigned)grid, 1, 1);
    cfg.blockDim = dim3(256, 1, 1);
    cfg.dynamicSmemBytes = 0;
    cfg.stream = 0;
    cudaLaunchAttribute attr[1];
    if (pdl) {
        attr[0].id = cudaLaunchAttributeProgrammaticStreamSerialization;
        attr[0].val.programmaticStreamSerializationAllowed = 1;
        cfg.attrs = attr;
        cfg.numAttrs = 1;
    }
    cudaLaunchKernelEx(&cfg, fused_kernel, verts, faces, out,
                       gA, nA, gR, nR, gN, nN);
}

extern "C" void kernel_launch(void* const* d_in, const int* in_sizes, int n_in,
                              void* d_out, int out_size) {
    const float* verts = (const float*)d_in[0];
    const int*   faces = (const int*)d_in[1];
    float*       out   = (float*)d_out;

    // L1: repack(0)
    launch_fused(VBLOCKS, false, verts, faces, out,
                 0, 0, 0, VBLOCKS, 0, 0);
    // L2: accum(0) + repack(1)
    launch_fused(ABLOCKS + VBLOCKS, true, verts, faces, out,
                 0, ABLOCKS, 1, VBLOCKS, 0, 0);
    // L3..L8: accum(g) + repack(g+1) + norm(g-1)
    for (int g = 1; g <= 6; g++) {
        launch_fused(ABLOCKS + 2 * VBLOCKS, true, verts, faces, out,
                     g, ABLOCKS, g + 1, VBLOCKS, g - 1, VBLOCKS);
    }
    // L9: accum(7) + norm(6)
    launch_fused(ABLOCKS + VBLOCKS, true, verts, faces, out,
                 7, ABLOCKS, 0, 0, 6, VBLOCKS);
    // L10: norm(7)
    launch_fused(VBLOCKS, true, verts, faces, out,
                 0, 0, 0, 0, 7, VBLOCKS);
}

// round 17
// speedup vs baseline: 1.1821x; 1.1821x over previous
#include <cuda_runtime.h>
#include <stdint.h>

// Problem constants (fixed by the dataset: B=32, V=200000, F=400000).
#define BB   32
#define VV   200000
#define FF   400000
#define NV   (BB * VV)      // 6,400,000
#define GB   8              // batches per group (lane sub-group)
#define NGRP (BB / GB)      // 4 groups

// Hybrid layouts (index = (g*VV + v)*GB + j, j = batch-in-group):
//   gathers:  g_vtx4  float4 (1 LDG.128 per vertex, instruction-cheap)
//   scatters: g_accXY float2 + g_accZ float (3 sectors per vertex, sector-cheap)
__device__ float4 g_vtx4 [NV];
__device__ float2 g_accXY[NV];
__device__ float  g_accZ [NV];

__device__ __forceinline__ void red_add_v2(float2* addr, float x, float y) {
    asm volatile("red.global.add.v2.f32 [%0], {%1, %2};"
                 :: "l"(addr), "f"(x), "f"(y) : "memory");
}
__device__ __forceinline__ void red_add_f(float* addr, float z) {
    asm volatile("red.global.add.f32 [%0], %1;"
                 :: "l"(addr), "f"(z) : "memory");
}

// Smem staging: 8 batch rows x 396 floats (384 data + 12 pad).
// 396 % 4 == 0 (float4 phase alignment); 396 mod 32 == 12 keeps the
// write/read pattern bank = (12j + 3vl + c) % 32 conflict-free.
#define SROW   396
#define VPB    128                      // vertices per DRAM block
#define VBLOCKS ((VV + VPB - 1) / VPB)  // 1563
#define ABLOCKS (FF * GB / 2 / 256)     // 6250  (2 faces per thread)

// ---------------------------------------------------------------------------
// Body 1: transpose-repack 128 vertices x 8 batches of group g, zero acc.
// No grid-dependency sync (fills predecessor tail under PDL).
// ---------------------------------------------------------------------------
__device__ __forceinline__ void repack_body(const float* __restrict__ verts,
                                            int g, int bx, float* s) {
    float4* s4 = reinterpret_cast<float4*>(s);
    const int t  = threadIdx.x;
    const int v0 = bx * VPB;
    const bool full = (v0 + VPB <= VV);

    if (full) {
#pragma unroll
        for (int rr = 0; rr < 3; rr++) {
            int idx   = rr * 256 + t;          // 0..767
            int b_loc = idx / 96;
            int k     = idx - b_loc * 96;
            const float4* src = reinterpret_cast<const float4*>(
                verts + (size_t)(g * GB + b_loc) * VV * 3 + (size_t)v0 * 3);
            s4[b_loc * (SROW / 4) + k] = src[k];
        }
    } else {
        for (int r = 0; r < 12; r++) {
            int idx   = r * 256 + t;           // 0..3071
            int b_loc = idx / 384;
            int off   = idx - b_loc * 384;
            int vl    = off / 3;
            if (v0 + vl < VV) {
                size_t src = (size_t)(g * GB + b_loc) * VV * 3 + (size_t)(v0 + vl) * 3
                             + (off - vl * 3);
                s[b_loc * SROW + off] = verts[src];
            }
        }
    }
    __syncthreads();

#pragma unroll
    for (int it = 0; it < 4; it++) {
        int w  = it * 256 + t;
        int vl = w >> 3;
        int j  = w & 7;
        int v  = v0 + vl;
        if (v < VV) {
            const float* p = &s[j * SROW + vl * 3];
            uint32_t dst = (uint32_t)(g * VV + v) * GB + j;
            g_vtx4 [dst] = make_float4(p[0], p[1], p[2], 0.0f);
            g_accXY[dst] = make_float2(0.0f, 0.0f);
            g_accZ [dst] = 0.0f;
        }
    }
}

// ---------------------------------------------------------------------------
// Body 2: accumulate face normals for group g. 2 faces per thread
// (measured-optimal: 32 regs, occ 86%, plain gathers).
// Needs repack(g) from the previous launch -> grid-dependency sync.
// ---------------------------------------------------------------------------
__device__ __forceinline__ void accum_body(const int* __restrict__ faces,
                                           int g, int bx) {
#if __CUDA_ARCH__ >= 900
    cudaGridDependencySynchronize();
#endif
    uint32_t t  = (uint32_t)bx * 256 + threadIdx.x;
    uint32_t j  = t & 7;
    uint32_t fp = t >> 3;               // face-pair index
    uint32_t base = (uint32_t)g * (VV * GB) + j;

    const int2* f2 = reinterpret_cast<const int2*>(faces) + 3 * (size_t)fp;
    int2 q0 = __ldg(&f2[0]);   // a0, a1
    int2 q1 = __ldg(&f2[1]);   // a2, b0
    int2 q2 = __ldg(&f2[2]);   // b1, b2

    uint32_t ia0 = base + (uint32_t)q0.x * GB;
    uint32_t ia1 = base + (uint32_t)q0.y * GB;
    uint32_t ia2 = base + (uint32_t)q1.x * GB;
    uint32_t ib0 = base + (uint32_t)q1.y * GB;
    uint32_t ib1 = base + (uint32_t)q2.x * GB;
    uint32_t ib2 = base + (uint32_t)q2.y * GB;

    float4 va0 = g_vtx4[ia0];
    float4 va1 = g_vtx4[ia1];
    float4 va2 = g_vtx4[ia2];
    float4 vb0 = g_vtx4[ib0];
    float4 vb1 = g_vtx4[ib1];
    float4 vb2 = g_vtx4[ib2];

    // Face A: e1 = v0 - v1; e2 = v2 - v1; n = cross(e2, e1)
    float e1x = va0.x - va1.x, e1y = va0.y - va1.y, e1z = va0.z - va1.z;
    float e2x = va2.x - va1.x, e2y = va2.y - va1.y, e2z = va2.z - va1.z;
    float nax = e2y * e1z - e2z * e1y;
    float nay = e2z * e1x - e2x * e1z;
    float naz = e2x * e1y - e2y * e1x;

    // Face B
    float g1x = vb0.x - vb1.x, g1y = vb0.y - vb1.y, g1z = vb0.z - vb1.z;
    float g2x = vb2.x - vb1.x, g2y = vb2.y - vb1.y, g2z = vb2.z - vb1.z;
    float nbx = g2y * g1z - g2z * g1y;
    float nby = g2z * g1x - g2x * g1z;
    float nbz = g2x * g1y - g2y * g1x;

    red_add_v2(&g_accXY[ia0], nax, nay);  red_add_f(&g_accZ[ia0], naz);
    red_add_v2(&g_accXY[ia1], nax, nay);  red_add_f(&g_accZ[ia1], naz);
    red_add_v2(&g_accXY[ia2], nax, nay);  red_add_f(&g_accZ[ia2], naz);
    red_add_v2(&g_accXY[ib0], nbx, nby);  red_add_f(&g_accZ[ib0], nbz);
    red_add_v2(&g_accXY[ib1], nbx, nby);  red_add_f(&g_accZ[ib1], nbz);
    red_add_v2(&g_accXY[ib2], nbx, nby);  red_add_f(&g_accZ[ib2], nbz);
}

// ---------------------------------------------------------------------------
// Body 3: normalize group g, write (B, V, 3). Grid-dependency sync.
// ---------------------------------------------------------------------------
__device__ __forceinline__ void norm_body(float* __restrict__ out,
                                          int g, int bx, float* s) {
#if __CUDA_ARCH__ >= 900
    cudaGridDependencySynchronize();
#endif
    float4* s4 = reinterpret_cast<float4*>(s);
    const int t  = threadIdx.x;
    const int v0 = bx * VPB;
    const bool full = (v0 + VPB <= VV);

#pragma unroll
    for (int it = 0; it < 4; it++) {
        int w  = it * 256 + t;
        int vl = w >> 3;
        int j  = w & 7;
        int v  = v0 + vl;
        if (v < VV) {
            uint32_t src = (uint32_t)(g * VV + v) * GB + j;
            float2 a = g_accXY[src];
            float  z = g_accZ [src];
            float sq = a.x * a.x + a.y * a.y + z * z;
            float sc = rsqrtf(fmaxf(sq, 1e-12f));
            float* p = &s[j * SROW + vl * 3];
            p[0] = a.x * sc;
            p[1] = a.y * sc;
            p[2] = z   * sc;
        }
    }
    __syncthreads();

    if (full) {
#pragma unroll
        for (int rr = 0; rr < 3; rr++) {
            int idx   = rr * 256 + t;
            int b_loc = idx / 96;
            int k     = idx - b_loc * 96;
            float4* dst = reinterpret_cast<float4*>(
                out + (size_t)(g * GB + b_loc) * VV * 3 + (size_t)v0 * 3);
            dst[k] = s4[b_loc * (SROW / 4) + k];
        }
    } else {
        for (int r = 0; r < 12; r++) {
            int idx   = r * 256 + t;
            int b_loc = idx / 384;
            int off   = idx - b_loc * 384;
            int vl    = off / 3;
            if (v0 + vl < VV) {
                size_t dst = (size_t)(g * GB + b_loc) * VV * 3 + (size_t)(v0 + vl) * 3
                             + (off - vl * 3);
                out[dst] = s[b_loc * SROW + off];
            }
        }
    }
}

// ---------------------------------------------------------------------------
// Fused dispatcher with EXACT interleave ratio K = total / D.
// DRAM job <=> (bx % K == K-1) && (bx / K < D); d = bx / K.
// Accum index a = bx - min(bx / K, D). Exactly D DRAM and nA accum jobs.
// ---------------------------------------------------------------------------
__global__ __launch_bounds__(256) void fused_kernel(
    const float* __restrict__ verts, const int* __restrict__ faces,
    float* __restrict__ out,
    int gA, int nA, int gR, int nR, int gN, int nN) {
    __shared__ float s[GB * SROW];

#if __CUDA_ARCH__ >= 900
    cudaTriggerProgrammaticLaunchCompletion();
#endif

    const int bx = blockIdx.x;
    const int D  = nR + nN;
    int d = -1;
    int a = -1;

    if (nA == 0) {
        d = bx;
    } else if (D == 0) {
        a = bx;
    } else {
        const int total = nA + D;
        const int K = total / D;                   // >= 1 since total >= D
        const int q = bx / K;
        if ((bx - q * K) == (K - 1) && q < D) {
            d = q;
        } else {
            a = bx - (q < D ? q : D);
        }
    }

    if (a >= 0) {
        accum_body(faces, gA, a);
    } else if (d < nR) {
        repack_body(verts, gR, d, s);
    } else {
        norm_body(out, gN, d - nR, s);
    }
}

// ---------------------------------------------------------------------------
// 6 PDL-stitched launches (measured-optimal pipeline depth 4):
//   L1: repack(0)
//   L2: accum(0) + repack(1)
//   L3: accum(1) + repack(2) + norm(0)
//   L4: accum(2) + repack(3) + norm(1)
//   L5: accum(3) + norm(2)
//   L6: norm(3)
// ---------------------------------------------------------------------------
static void launch_fused(int grid, bool pdl,
                         const float* verts, const int* faces, float* out,
                         int gA, int nA, int gR, int nR, int gN, int nN) {
    cudaLaunchConfig_t cfg = {};
    cfg.gridDim  = dim3((unsigned)grid, 1, 1);
    cfg.blockDim = dim3(256, 1, 1);
    cfg.dynamicSmemBytes = 0;
    cfg.stream = 0;
    cudaLaunchAttribute attr[1];
    if (pdl) {
        attr[0].id = cudaLaunchAttributeProgrammaticStreamSerialization;
        attr[0].val.programmaticStreamSerializationAllowed = 1;
        cfg.attrs = attr;
        cfg.numAttrs = 1;
    }
    cudaLaunchKernelEx(&cfg, fused_kernel, verts, faces, out,
                       gA, nA, gR, nR, gN, nN);
}

extern "C" void kernel_launch(void* const* d_in, const int* in_sizes, int n_in,
                              void* d_out, int out_size) {
    const float* verts = (const float*)d_in[0];
    const int*   faces = (const int*)d_in[1];
    float*       out   = (float*)d_out;

    launch_fused(VBLOCKS, false, verts, faces, out, 0, 0, 0, VBLOCKS, 0, 0);
    launch_fused(ABLOCKS + VBLOCKS, true, verts, faces, out,
                 0, ABLOCKS, 1, VBLOCKS, 0, 0);
    launch_fused(ABLOCKS + 2 * VBLOCKS, true, verts, faces, out,
                 1, ABLOCKS, 2, VBLOCKS, 0, VBLOCKS);
    launch_fused(ABLOCKS + 2 * VBLOCKS, true, verts, faces, out,
                 2, ABLOCKS, 3, VBLOCKS, 1, VBLOCKS);
    launch_fused(ABLOCKS + VBLOCKS, true, verts, faces, out,
                 3, ABLOCKS, 0, 0, 2, VBLOCKS);
    launch_fused(VBLOCKS, true, verts, faces, out, 0, 0, 0, 0, 3, VBLOCKS);
}